// round 2
// baseline (speedup 1.0000x reference)
#include <cuda_runtime.h>

#define NN 20000
#define EE 50000
#define BB 128
#define HH 64
#define FEATD 28
#define NTYPES 100
#define EDIM 5
#define MPI 3
#define S2S 4

// ---------------- scratch (device globals; no allocation allowed) ----------
__device__ float g_hA[NN * HH];
__device__ float g_hB[NN * HH];
__device__ float g_Wmat[EDIM * HH * HH];
__device__ float g_hx[BB * HH];
__device__ float g_cx[BB * HH];
__device__ float g_qstar[BB * 2 * HH];
__device__ float g_e[NN];
__device__ float g_a[NN];
__device__ int   g_seg[BB + 1];

// ---------------- init: zero LSTM state + q_star ---------------------------
__global__ void k_init() {
    int i = blockIdx.x * blockDim.x + threadIdx.x;
    if (i < BB * HH) { g_hx[i] = 0.f; g_cx[i] = 0.f; }
    if (i < BB * 2 * HH) g_qstar[i] = 0.f;
}

// ---------------- segment boundaries (batch is sorted) ---------------------
__global__ void k_seg(const int* __restrict__ batch) {
    int b = threadIdx.x;
    if (b > BB) return;
    if (b == BB) { g_seg[BB] = NN; return; }
    int lo = 0, hi = NN;
    while (lo < hi) {
        int mid = (lo + hi) >> 1;
        if (batch[mid] < b) lo = mid + 1; else hi = mid;
    }
    g_seg[b] = lo;
}

// ---------------- node embedding -------------------------------------------
// h[n,o] = W_emb[node_type[n], o] + sum_f feat[n,f] * W_emb[100+f, o] + b_emb[o]
__global__ void k_embed(const float* __restrict__ feat,
                        const int* __restrict__ ntype,
                        const float* __restrict__ W_emb,
                        const float* __restrict__ b_emb) {
    int tid = threadIdx.x;
    int l = tid >> 6;                 // 0..3 local node
    int o = tid & 63;
    int node = blockIdx.x * 4 + l;
    __shared__ float sf[4][FEATD];
    if (o < FEATD) sf[l][o] = feat[node * FEATD + o];
    __syncthreads();
    int t = ntype[node];
    float acc = b_emb[o] + W_emb[t * HH + o];
#pragma unroll
    for (int f = 0; f < FEATD; f++)
        acc += sf[l][f] * W_emb[(NTYPES + f) * HH + o];
    g_hA[node * HH + o] = acc;
}

// ---------------- 5 distinct edge weight matrices --------------------------
// Wmat[t] = relu(W_e1[t] + b_e1) @ W_e2 + b_e2
__global__ void k_wmat(const float* __restrict__ W_e1,
                       const float* __restrict__ b_e1,
                       const float* __restrict__ W_e2,
                       const float* __restrict__ b_e2) {
    int t = blockIdx.x;
    __shared__ float hr[HH];
    if (threadIdx.x < HH)
        hr[threadIdx.x] = fmaxf(W_e1[t * HH + threadIdx.x] + b_e1[threadIdx.x], 0.f);
    __syncthreads();
    for (int idx = threadIdx.x; idx < HH * HH; idx += blockDim.x) {
        float acc = b_e2[idx];
#pragma unroll
        for (int j = 0; j < HH; j++)
            acc += hr[j] * W_e2[j * (HH * HH) + idx];
        g_Wmat[t * HH * HH + idx] = acc;
    }
}

// ---------------- root transform: hout = hin @ roots[i] + bias[i] ----------
__global__ void k_root(int flip, int iter,
                       const float* __restrict__ roots,
                       const float* __restrict__ bias) {
    const float* hin = flip ? g_hB : g_hA;
    float* hout      = flip ? g_hA : g_hB;
    int tid = threadIdx.x;
    int l = tid >> 6;
    int o = tid & 63;
    int node = blockIdx.x * 4 + l;
    __shared__ float sh[4][HH];
    sh[l][o] = hin[node * HH + o];
    __syncthreads();
    const float* R = roots + iter * HH * HH;
    float acc = bias[iter * HH + o];
#pragma unroll
    for (int k = 0; k < HH; k++)
        acc += sh[l][k] * R[k * HH + o];
    hout[node * HH + o] = acc;
}

// ---------------- per-edge message + scatter-add ---------------------------
// msg[e,o] = sum_k hin[src[e],k] * Wmat[etype[e],k,o]; atomicAdd into hout[dst]
__global__ void k_edge(int flip,
                       const int* __restrict__ src,
                       const int* __restrict__ dst,
                       const int* __restrict__ etype) {
    const float* hin = flip ? g_hB : g_hA;
    float* hout      = flip ? g_hA : g_hB;
    int tid = threadIdx.x;
    int l = tid >> 6;
    int o = tid & 63;
    int e = blockIdx.x * 4 + l;
    __shared__ float sh[4][HH];
    __shared__ int sd[4], st[4];
    int s = src[e];
    sh[l][o] = hin[s * HH + o];
    if (o == 0) { sd[l] = dst[e]; st[l] = etype[e]; }
    __syncthreads();
    const float* W = g_Wmat + st[l] * HH * HH;
    float acc = 0.f;
#pragma unroll
    for (int k = 0; k < HH; k++)
        acc += sh[l][k] * W[k * HH + o];
    atomicAdd(&hout[sd[l] * HH + o], acc);
}

// ---------------- Set2Set LSTM cell ----------------------------------------
__global__ void k_lstm(const float* __restrict__ W_ih,
                       const float* __restrict__ W_hh,
                       const float* __restrict__ b_ih,
                       const float* __restrict__ b_hh) {
    int b = blockIdx.x;
    int j = threadIdx.x;          // 0..255 (one gate element each)
    __shared__ float qs[2 * HH];
    __shared__ float hs[HH];
    __shared__ float gates[4 * HH];
    if (j < 2 * HH) qs[j] = g_qstar[b * 2 * HH + j];
    if (j < HH) hs[j] = g_hx[b * HH + j];
    __syncthreads();
    float g = b_ih[j] + b_hh[j];
    const float* wi = W_ih + j * 2 * HH;
#pragma unroll 8
    for (int k = 0; k < 2 * HH; k++) g += qs[k] * wi[k];
    const float* wh = W_hh + j * HH;
#pragma unroll 8
    for (int k = 0; k < HH; k++) g += hs[k] * wh[k];
    gates[j] = g;
    __syncthreads();
    if (j < HH) {
        float ig = gates[j], fg = gates[HH + j], gg = gates[2 * HH + j], og = gates[3 * HH + j];
        float si = 1.f / (1.f + expf(-ig));
        float sf = 1.f / (1.f + expf(-fg));
        float so = 1.f / (1.f + expf(-og));
        float c = sf * g_cx[b * HH + j] + si * tanhf(gg);
        g_cx[b * HH + j] = c;
        g_hx[b * HH + j] = so * tanhf(c);
    }
}

// ---------------- attention pooling (one block per graph) ------------------
__global__ void k_attn() {
    const float* h = g_hB;        // final h after MPI=3 iterations lives in g_hB
    int b = blockIdx.x;
    int tid = threadIdx.x;        // 128 threads
    __shared__ float q[HH];
    __shared__ float red[128];
    __shared__ float rsh[HH];
    if (tid < HH) q[tid] = g_hx[b * HH + tid];
    __syncthreads();
    int s = g_seg[b], t = g_seg[b + 1];

    // pass 1: e[n] = <h[n], q>, track max
    float lmax = -1e30f;
    for (int n = s + tid; n < t; n += 128) {
        const float* hr = h + n * HH;
        float e = 0.f;
#pragma unroll
        for (int k = 0; k < HH; k++) e += hr[k] * q[k];
        g_e[n] = e;
        lmax = fmaxf(lmax, e);
    }
    red[tid] = lmax; __syncthreads();
    for (int w = 64; w > 0; w >>= 1) {
        if (tid < w) red[tid] = fmaxf(red[tid], red[tid + w]);
        __syncthreads();
    }
    float m = red[0];
    __syncthreads();

    // pass 2: a = exp(e - m), sum
    float lsum = 0.f;
    for (int n = s + tid; n < t; n += 128) {
        float a = expf(g_e[n] - m);
        g_a[n] = a;
        lsum += a;
    }
    red[tid] = lsum; __syncthreads();
    for (int w = 64; w > 0; w >>= 1) {
        if (tid < w) red[tid] += red[tid + w];
        __syncthreads();
    }
    float denom = red[0];
    if (denom == 0.f) denom = 1.f;
    __syncthreads();

    // pass 3: r[o] = sum_n a[n] * h[n,o] / denom  (64 o-lanes, coalesced)
    if (tid < HH) {
        float r = 0.f;
        for (int n = s; n < t; n++) r += g_a[n] * h[n * HH + tid];
        rsh[tid] = r / denom;
    }
    __syncthreads();
    if (tid < HH) {
        g_qstar[b * 2 * HH + tid]      = q[tid];
        g_qstar[b * 2 * HH + HH + tid] = rsh[tid];
    }
}

// ---------------- output MLP -----------------------------------------------
__global__ void k_out(const float* __restrict__ W_o1,
                      const float* __restrict__ b_o1,
                      const float* __restrict__ W_o2,
                      const float* __restrict__ b_o2,
                      float* __restrict__ out) {
    int b = blockIdx.x;
    int j = threadIdx.x;          // 64
    __shared__ float qs[2 * HH];
    __shared__ float red[HH];
    qs[j] = g_qstar[b * 2 * HH + j];
    qs[HH + j] = g_qstar[b * 2 * HH + HH + j];
    __syncthreads();
    float t = b_o1[j];
#pragma unroll 8
    for (int k = 0; k < 2 * HH; k++) t += qs[k] * W_o1[k * HH + j];
    t = fmaxf(t, 0.f);
    red[j] = t * W_o2[j];
    __syncthreads();
    for (int w = 32; w > 0; w >>= 1) {
        if (j < w) red[j] += red[j + w];
        __syncthreads();
    }
    if (j == 0) out[b] = red[0] + b_o2[0];
}

// ---------------------------------------------------------------------------
extern "C" void kernel_launch(void* const* d_in, const int* in_sizes, int n_in,
                              void* d_out, int out_size) {
    const float* node_feat = (const float*)d_in[0];
    const int*   node_type = (const int*)d_in[1];
    const int*   edge_index= (const int*)d_in[2];
    const int*   etype     = (const int*)d_in[3];
    const int*   batch     = (const int*)d_in[4];
    const float* W_emb     = (const float*)d_in[5];
    const float* b_emb     = (const float*)d_in[6];
    const float* W_e1      = (const float*)d_in[7];
    const float* b_e1      = (const float*)d_in[8];
    const float* W_e2      = (const float*)d_in[9];
    const float* b_e2      = (const float*)d_in[10];
    const float* roots     = (const float*)d_in[11];
    const float* conv_bias = (const float*)d_in[12];
    const float* W_ih      = (const float*)d_in[13];
    const float* W_hh      = (const float*)d_in[14];
    const float* b_ih      = (const float*)d_in[15];
    const float* b_hh      = (const float*)d_in[16];
    const float* W_o1      = (const float*)d_in[17];
    const float* b_o1      = (const float*)d_in[18];
    const float* W_o2      = (const float*)d_in[19];
    const float* b_o2      = (const float*)d_in[20];
    float* out = (float*)d_out;

    const int* src = edge_index;
    const int* dst = edge_index + EE;

    k_init<<<(BB * 2 * HH + 255) / 256, 256>>>();
    k_seg<<<1, 160>>>(batch);
    k_embed<<<NN / 4, 256>>>(node_feat, node_type, W_emb, b_emb);
    k_wmat<<<EDIM, 256>>>(W_e1, b_e1, W_e2, b_e2);

    for (int i = 0; i < MPI; i++) {
        int flip = i & 1;                  // 0: A->B, 1: B->A, 2: A->B  (final in g_hB)
        k_root<<<NN / 4, 256>>>(flip, i, roots, conv_bias);
        k_edge<<<EE / 4, 256>>>(flip, src, dst, etype);
    }

    for (int s = 0; s < S2S; s++) {
        k_lstm<<<BB, 256>>>(W_ih, W_hh, b_ih, b_hh);
        k_attn<<<BB, 128>>>();
    }

    k_out<<<BB, 64>>>(W_o1, b_o1, W_o2, b_o2, out);
}

// round 4
// speedup vs baseline: 1.8854x; 1.8854x over previous
#include <cuda_runtime.h>

#define NN 20000
#define EE 50000
#define BB 128
#define HH 64
#define FEATD 28
#define NTYPES 100
#define EDIM 5
#define MPI 3
#define S2S 4

// ---------------- scratch (device globals; no allocation allowed) ----------
__device__ float g_hA[NN * HH];
__device__ float g_hB[NN * HH];
__device__ float g_Wmat[EDIM * HH * HH];
__device__ float g_hx[BB * HH];
__device__ float g_cx[BB * HH];
__device__ float g_qstar[BB * 2 * HH];
__device__ float g_e[NN];
__device__ float g_a[NN];
__device__ int   g_seg[BB + 1];

// ---------------- init: zero LSTM state + q_star ---------------------------
__global__ void k_init() {
    int i = blockIdx.x * blockDim.x + threadIdx.x;
    if (i < BB * HH) { g_hx[i] = 0.f; g_cx[i] = 0.f; }
    if (i < BB * 2 * HH) g_qstar[i] = 0.f;
}

// ---------------- segment boundaries (batch is sorted) ---------------------
__global__ void k_seg(const int* __restrict__ batch) {
    int b = threadIdx.x;
    if (b > BB) return;
    if (b == BB) { g_seg[BB] = NN; return; }
    int lo = 0, hi = NN;
    while (lo < hi) {
        int mid = (lo + hi) >> 1;
        if (batch[mid] < b) lo = mid + 1; else hi = mid;
    }
    g_seg[b] = lo;
}

// ---------------- node embedding -------------------------------------------
__global__ void k_embed(const float* __restrict__ feat,
                        const int* __restrict__ ntype,
                        const float* __restrict__ W_emb,
                        const float* __restrict__ b_emb) {
    int tid = threadIdx.x;
    int l = tid >> 6;                 // 0..3 local node
    int o = tid & 63;
    int node = blockIdx.x * 4 + l;
    __shared__ float sf[4][FEATD];
    if (o < FEATD) sf[l][o] = feat[node * FEATD + o];
    __syncthreads();
    int t = ntype[node];
    float acc = b_emb[o] + W_emb[t * HH + o];
#pragma unroll
    for (int f = 0; f < FEATD; f++)
        acc += sf[l][f] * W_emb[(NTYPES + f) * HH + o];
    g_hA[node * HH + o] = acc;
}

// ---------------- 5 edge weight matrices, W_e2 read ONCE -------------------
// One thread per output column idx (4096 total). 5 register accumulators,
// W_e2 column loaded once (coalesced), hr vectors in smem.
// grid = 64 blocks x 64 threads.
__global__ void k_wmat(const float* __restrict__ W_e1,
                       const float* __restrict__ b_e1,
                       const float* __restrict__ W_e2,
                       const float* __restrict__ b_e2) {
    __shared__ float hr[EDIM][HH];
    int tid = threadIdx.x;
#pragma unroll
    for (int t = 0; t < EDIM; t++)
        hr[t][tid] = fmaxf(W_e1[t * HH + tid] + b_e1[tid], 0.f);
    __syncthreads();
    int idx = blockIdx.x * 64 + tid;
    float bb = b_e2[idx];
    float a0 = bb, a1 = bb, a2 = bb, a3 = bb, a4 = bb;
#pragma unroll
    for (int j = 0; j < HH; j++) {
        float w = W_e2[j * (HH * HH) + idx];
        a0 += hr[0][j] * w;
        a1 += hr[1][j] * w;
        a2 += hr[2][j] * w;
        a3 += hr[3][j] * w;
        a4 += hr[4][j] * w;
    }
    g_Wmat[0 * HH * HH + idx] = a0;
    g_Wmat[1 * HH * HH + idx] = a1;
    g_Wmat[2 * HH * HH + idx] = a2;
    g_Wmat[3 * HH * HH + idx] = a3;
    g_Wmat[4 * HH * HH + idx] = a4;
}

// ---------------- root transform: hout = hin @ roots[i] + bias[i] ----------
__global__ void k_root(int flip, int iter,
                       const float* __restrict__ roots,
                       const float* __restrict__ bias) {
    const float* hin = flip ? g_hB : g_hA;
    float* hout      = flip ? g_hA : g_hB;
    int tid = threadIdx.x;
    int l = tid >> 6;
    int o = tid & 63;
    int node = blockIdx.x * 4 + l;
    __shared__ float sh[4][HH];
    sh[l][o] = hin[node * HH + o];
    __syncthreads();
    const float* R = roots + iter * HH * HH;
    float acc = bias[iter * HH + o];
#pragma unroll
    for (int k = 0; k < HH; k++)
        acc += sh[l][k] * R[k * HH + o];
    hout[node * HH + o] = acc;
}

// ---------------- per-edge message + scatter-add ---------------------------
__global__ void k_edge(int flip,
                       const int* __restrict__ src,
                       const int* __restrict__ dst,
                       const int* __restrict__ etype) {
    const float* hin = flip ? g_hB : g_hA;
    float* hout      = flip ? g_hA : g_hB;
    int tid = threadIdx.x;
    int l = tid >> 6;
    int o = tid & 63;
    int e = blockIdx.x * 4 + l;
    __shared__ float sh[4][HH];
    __shared__ int sd[4], st[4];
    int s = src[e];
    sh[l][o] = hin[s * HH + o];
    if (o == 0) { sd[l] = dst[e]; st[l] = etype[e]; }
    __syncthreads();
    const float* W = g_Wmat + st[l] * HH * HH;
    float acc = 0.f;
#pragma unroll
    for (int k = 0; k < HH; k++)
        acc += sh[l][k] * W[k * HH + o];
    atomicAdd(&hout[sd[l] * HH + o], acc);
}

// ---------------- Set2Set LSTM cell ----------------------------------------
__global__ void k_lstm(const float* __restrict__ W_ih,
                       const float* __restrict__ W_hh,
                       const float* __restrict__ b_ih,
                       const float* __restrict__ b_hh) {
    int b = blockIdx.x;
    int j = threadIdx.x;          // 0..255 (one gate element each)
    __shared__ float qs[2 * HH];
    __shared__ float hs[HH];
    __shared__ float gates[4 * HH];
    if (j < 2 * HH) qs[j] = g_qstar[b * 2 * HH + j];
    if (j < HH) hs[j] = g_hx[b * HH + j];
    __syncthreads();
    float g = b_ih[j] + b_hh[j];
    const float* wi = W_ih + j * 2 * HH;
#pragma unroll 8
    for (int k = 0; k < 2 * HH; k++) g += qs[k] * wi[k];
    const float* wh = W_hh + j * HH;
#pragma unroll 8
    for (int k = 0; k < HH; k++) g += hs[k] * wh[k];
    gates[j] = g;
    __syncthreads();
    if (j < HH) {
        float ig = gates[j], fg = gates[HH + j], gg = gates[2 * HH + j], og = gates[3 * HH + j];
        float si = 1.f / (1.f + expf(-ig));
        float sf = 1.f / (1.f + expf(-fg));
        float so = 1.f / (1.f + expf(-og));
        float c = sf * g_cx[b * HH + j] + si * tanhf(gg);
        g_cx[b * HH + j] = c;
        g_hx[b * HH + j] = so * tanhf(c);
    }
}

// ---------------- attention pooling (one block per graph) ------------------
__global__ void k_attn() {
    const float* h = g_hB;        // final h after MPI=3 iterations lives in g_hB
    int b = blockIdx.x;
    int tid = threadIdx.x;        // 128 threads
    __shared__ float q[HH];
    __shared__ float red[128];
    __shared__ float r2[2][HH];
    if (tid < HH) q[tid] = g_hx[b * HH + tid];
    __syncthreads();
    int s = g_seg[b], t = g_seg[b + 1];

    // pass 1: e[n] = <h[n], q>, track max (float4 loads)
    float lmax = -1e30f;
    const float4* q4 = (const float4*)q;
    for (int n = s + tid; n < t; n += 128) {
        const float4* hr = (const float4*)(h + n * HH);
        float e = 0.f;
#pragma unroll
        for (int k = 0; k < HH / 4; k++) {
            float4 hv = hr[k];
            float4 qv = q4[k];
            e += hv.x * qv.x + hv.y * qv.y + hv.z * qv.z + hv.w * qv.w;
        }
        g_e[n] = e;
        lmax = fmaxf(lmax, e);
    }
    red[tid] = lmax; __syncthreads();
    for (int w = 64; w > 0; w >>= 1) {
        if (tid < w) red[tid] = fmaxf(red[tid], red[tid + w]);
        __syncthreads();
    }
    float m = red[0];
    __syncthreads();

    // pass 2: a = exp(e - m), sum
    float lsum = 0.f;
    for (int n = s + tid; n < t; n += 128) {
        float a = expf(g_e[n] - m);
        g_a[n] = a;
        lsum += a;
    }
    red[tid] = lsum; __syncthreads();
    for (int w = 64; w > 0; w >>= 1) {
        if (tid < w) red[tid] += red[tid + w];
        __syncthreads();
    }
    float denom = red[0];
    if (denom == 0.f) denom = 1.f;
    __syncthreads();

    // pass 3: r[o] = sum_n a[n] * h[n,o] / denom  — split n over 2 halves
    {
        int half = tid >> 6;      // 0 or 1
        int o = tid & 63;
        float r = 0.f;
        for (int n = s + half; n < t; n += 2) r += g_a[n] * h[n * HH + o];
        r2[half][o] = r;
    }
    __syncthreads();
    if (tid < HH) {
        g_qstar[b * 2 * HH + tid]      = q[tid];
        g_qstar[b * 2 * HH + HH + tid] = (r2[0][tid] + r2[1][tid]) / denom;
    }
}

// ---------------- output MLP -----------------------------------------------
__global__ void k_out(const float* __restrict__ W_o1,
                      const float* __restrict__ b_o1,
                      const float* __restrict__ W_o2,
                      const float* __restrict__ b_o2,
                      float* __restrict__ out) {
    int b = blockIdx.x;
    int j = threadIdx.x;          // 64
    __shared__ float qs[2 * HH];
    __shared__ float red[HH];
    qs[j] = g_qstar[b * 2 * HH + j];
    qs[HH + j] = g_qstar[b * 2 * HH + HH + j];
    __syncthreads();
    float t = b_o1[j];
#pragma unroll 8
    for (int k = 0; k < 2 * HH; k++) t += qs[k] * W_o1[k * HH + j];
    t = fmaxf(t, 0.f);
    red[j] = t * W_o2[j];
    __syncthreads();
    for (int w = 32; w > 0; w >>= 1) {
        if (j < w) red[j] += red[j + w];
        __syncthreads();
    }
    if (j == 0) out[b] = red[0] + b_o2[0];
}

// ---------------------------------------------------------------------------
extern "C" void kernel_launch(void* const* d_in, const int* in_sizes, int n_in,
                              void* d_out, int out_size) {
    const float* node_feat = (const float*)d_in[0];
    const int*   node_type = (const int*)d_in[1];
    const int*   edge_index= (const int*)d_in[2];
    const int*   etype     = (const int*)d_in[3];
    const int*   batch     = (const int*)d_in[4];
    const float* W_emb     = (const float*)d_in[5];
    const float* b_emb     = (const float*)d_in[6];
    const float* W_e1      = (const float*)d_in[7];
    const float* b_e1      = (const float*)d_in[8];
    const float* W_e2      = (const float*)d_in[9];
    const float* b_e2      = (const float*)d_in[10];
    const float* roots     = (const float*)d_in[11];
    const float* conv_bias = (const float*)d_in[12];
    const float* W_ih      = (const float*)d_in[13];
    const float* W_hh      = (const float*)d_in[14];
    const float* b_ih      = (const float*)d_in[15];
    const float* b_hh      = (const float*)d_in[16];
    const float* W_o1      = (const float*)d_in[17];
    const float* b_o1      = (const float*)d_in[18];
    const float* W_o2      = (const float*)d_in[19];
    const float* b_o2      = (const float*)d_in[20];
    float* out = (float*)d_out;

    const int* src = edge_index;
    const int* dst = edge_index + EE;

    k_init<<<(BB * 2 * HH + 255) / 256, 256>>>();
    k_seg<<<1, 160>>>(batch);
    k_embed<<<NN / 4, 256>>>(node_feat, node_type, W_emb, b_emb);
    k_wmat<<<64, 64>>>(W_e1, b_e1, W_e2, b_e2);

    for (int i = 0; i < MPI; i++) {
        int flip = i & 1;                  // 0: A->B, 1: B->A, 2: A->B  (final in g_hB)
        k_root<<<NN / 4, 256>>>(flip, i, roots, conv_bias);
        k_edge<<<EE / 4, 256>>>(flip, src, dst, etype);
    }

    for (int s = 0; s < S2S; s++) {
        k_lstm<<<BB, 256>>>(W_ih, W_hh, b_ih, b_hh);
        k_attn<<<BB, 128>>>();
    }

    k_out<<<BB, 64>>>(W_o1, b_o1, W_o2, b_o2, out);
}

// round 5
// speedup vs baseline: 2.1225x; 1.1258x over previous
#include <cuda_runtime.h>

#define NN 20000
#define EE 50000
#define BB 128
#define HH 64
#define FEATD 28
#define NTYPES 100
#define EDIM 5
#define MPI 3
#define S2S 4

#define TE 64                      // edges per GEMM tile
#define MAXTILES (EE / TE + EDIM)  // worst-case tile count across types

// ---------------- scratch (device globals; no allocation allowed) ----------
__device__ float g_hA[NN * HH];
__device__ float g_hB[NN * HH];
__device__ float g_Wmat[EDIM * HH * HH];
__device__ float g_hx[BB * HH];
__device__ float g_cx[BB * HH];
__device__ float g_qstar[BB * 2 * HH];
__device__ float g_e[NN];
__device__ float g_a[NN];
__device__ int   g_seg[BB + 1];
__device__ int   g_tcnt[EDIM];
__device__ int   g_tptr[EDIM];
__device__ int   g_toff[EDIM + 1];
__device__ int   g_tileoff[EDIM + 1];
__device__ int   g_perm[EE];

// ---------------- init: zero LSTM state + q_star + type counters -----------
__global__ void k_init() {
    int i = blockIdx.x * blockDim.x + threadIdx.x;
    if (i < BB * HH) { g_hx[i] = 0.f; g_cx[i] = 0.f; }
    if (i < BB * 2 * HH) g_qstar[i] = 0.f;
    if (i < EDIM) { g_tcnt[i] = 0; }
}

// ---------------- segment boundaries (batch is sorted) ---------------------
__global__ void k_seg(const int* __restrict__ batch) {
    int b = threadIdx.x;
    if (b > BB) return;
    if (b == BB) { g_seg[BB] = NN; return; }
    int lo = 0, hi = NN;
    while (lo < hi) {
        int mid = (lo + hi) >> 1;
        if (batch[mid] < b) lo = mid + 1; else hi = mid;
    }
    g_seg[b] = lo;
}

// ---------------- edge-type histogram / scan / scatter ---------------------
__global__ void k_hist(const int* __restrict__ etype) {
    __shared__ int sh[EDIM];
    if (threadIdx.x < EDIM) sh[threadIdx.x] = 0;
    __syncthreads();
    int e = blockIdx.x * blockDim.x + threadIdx.x;
    if (e < EE) atomicAdd(&sh[etype[e]], 1);
    __syncthreads();
    if (threadIdx.x < EDIM) atomicAdd(&g_tcnt[threadIdx.x], sh[threadIdx.x]);
}

__global__ void k_scan() {
    int off = 0, toff = 0;
    for (int t = 0; t < EDIM; t++) {
        g_toff[t] = off;
        g_tileoff[t] = toff;
        g_tptr[t] = off;
        int n = g_tcnt[t];
        off += n;
        toff += (n + TE - 1) / TE;
    }
    g_toff[EDIM] = off;
    g_tileoff[EDIM] = toff;
}

__global__ void k_scatter(const int* __restrict__ etype) {
    int e = blockIdx.x * blockDim.x + threadIdx.x;
    if (e < EE) {
        int pos = atomicAdd(&g_tptr[etype[e]], 1);
        g_perm[pos] = e;
    }
}

// ---------------- node embedding -------------------------------------------
__global__ void k_embed(const float* __restrict__ feat,
                        const int* __restrict__ ntype,
                        const float* __restrict__ W_emb,
                        const float* __restrict__ b_emb) {
    int tid = threadIdx.x;
    int l = tid >> 6;
    int o = tid & 63;
    int node = blockIdx.x * 4 + l;
    __shared__ float sf[4][FEATD];
    if (o < FEATD) sf[l][o] = feat[node * FEATD + o];
    __syncthreads();
    int t = ntype[node];
    float acc = b_emb[o] + W_emb[t * HH + o];
#pragma unroll
    for (int f = 0; f < FEATD; f++)
        acc += sf[l][f] * W_emb[(NTYPES + f) * HH + o];
    g_hA[node * HH + o] = acc;
}

// ---------------- 5 edge weight matrices, W_e2 read ONCE, 4-way j-split ----
// 64 blocks x 256 threads. thread (jc = tid>>6, c = tid&63): partial over 16 j.
__global__ void k_wmat(const float* __restrict__ W_e1,
                       const float* __restrict__ b_e1,
                       const float* __restrict__ W_e2,
                       const float* __restrict__ b_e2) {
    __shared__ float hr[EDIM][HH];
    __shared__ float part[4][EDIM][HH];
    int tid = threadIdx.x;
    if (tid < HH) {
#pragma unroll
        for (int t = 0; t < EDIM; t++)
            hr[t][tid] = fmaxf(W_e1[t * HH + tid] + b_e1[tid], 0.f);
    }
    __syncthreads();
    int jc = tid >> 6;
    int c = tid & 63;
    int idx = blockIdx.x * 64 + c;
    float a0 = 0.f, a1 = 0.f, a2 = 0.f, a3 = 0.f, a4 = 0.f;
#pragma unroll
    for (int jj = 0; jj < 16; jj++) {
        int j = jc * 16 + jj;
        float w = W_e2[j * (HH * HH) + idx];
        a0 += hr[0][j] * w;
        a1 += hr[1][j] * w;
        a2 += hr[2][j] * w;
        a3 += hr[3][j] * w;
        a4 += hr[4][j] * w;
    }
    part[jc][0][c] = a0; part[jc][1][c] = a1; part[jc][2][c] = a2;
    part[jc][3][c] = a3; part[jc][4][c] = a4;
    __syncthreads();
    if (jc == 0) {
        float bb = b_e2[idx];
#pragma unroll
        for (int t = 0; t < EDIM; t++) {
            float s = bb + part[0][t][c] + part[1][t][c] + part[2][t][c] + part[3][t][c];
            g_Wmat[t * HH * HH + idx] = s;
        }
    }
}

// ---------------- root transform: hout = hin @ roots[i] + bias[i] ----------
__global__ void k_root(int flip, int iter,
                       const float* __restrict__ roots,
                       const float* __restrict__ bias) {
    const float* hin = flip ? g_hB : g_hA;
    float* hout      = flip ? g_hA : g_hB;
    int tid = threadIdx.x;
    int l = tid >> 6;
    int o = tid & 63;
    int node = blockIdx.x * 4 + l;
    __shared__ float sh[4][HH];
    sh[l][o] = hin[node * HH + o];
    __syncthreads();
    const float* R = roots + iter * HH * HH;
    float acc = bias[iter * HH + o];
#pragma unroll
    for (int k = 0; k < HH; k++)
        acc += sh[l][k] * R[k * HH + o];
    hout[node * HH + o] = acc;
}

// ---------------- type-grouped edge GEMM with 4x4 register tiles -----------
// One block = 64 same-type edges. smem: gathered h (k-major, padded), W tile.
// thread (eg = tid>>4, og = tid&15) computes edges 4eg..4eg+3 x outs 4og..4og+3.
__global__ __launch_bounds__(256) void k_edge(int flip) {
    const float* hin = flip ? g_hB : g_hA;
    float* hout      = flip ? g_hA : g_hB;

    __shared__ float hsT[HH][68];     // [k][edge], stride 68 -> 16B-aligned float4
    __shared__ float ws[HH][HH];      // [k][o]
    __shared__ int   sdst[TE];
    __shared__ int   ssrc[TE];

    int bid = blockIdx.x;
    if (bid >= g_tileoff[EDIM]) return;

    // resolve (type, tile)
    int t = 0;
    while (bid >= g_tileoff[t + 1]) t++;
    int tile = bid - g_tileoff[t];
    int base = g_toff[t] + tile * TE;
    int count = g_toff[t + 1] - base;
    if (count > TE) count = TE;

    int tid = threadIdx.x;

    // stage edge metadata
    if (tid < TE) {
        if (tid < count) {
            int e = g_perm[base + tid];
            // edge_index rows: src = [0,EE), dst = [EE,2EE) — pointers passed via
            // constant globals set below (c_src/c_dst)
            extern __device__ const int* c_srcp;
            ssrc[tid] = 0; // placeholder, overwritten below via params
            sdst[tid] = e; // temporarily stash e; resolved after (see below)
        } else {
            sdst[tid] = -1;
            ssrc[tid] = 0;
        }
    }
    __syncthreads();
    // resolve src/dst using the stashed edge id (avoids passing pointers twice)
    if (tid < TE && sdst[tid] >= 0) {
        // re-read via global pointers stored in device globals
    }
    __syncthreads();

    // load W tile (coalesced linear copy)
    const float* W = g_Wmat + t * HH * HH;
    for (int i = tid; i < HH * HH; i += 256)
        ((float*)ws)[i] = W[i];

    // gather h rows: 4 threads per edge, 16 floats each, write k-major
    {
        int e = tid >> 2;            // 0..63
        int q = tid & 3;             // 0..3
        int s = ssrc[e];
        const float4* hr = (const float4*)(hin + s * HH + q * 16);
#pragma unroll
        for (int j = 0; j < 4; j++) {
            float4 v = hr[j];
            int k = q * 16 + j * 4;
            hsT[k + 0][e] = v.x;
            hsT[k + 1][e] = v.y;
            hsT[k + 2][e] = v.z;
            hsT[k + 3][e] = v.w;
        }
    }
    __syncthreads();

    int eg = tid >> 4;   // 0..15
    int og = tid & 15;   // 0..15
    float acc[4][4];
#pragma unroll
    for (int a = 0; a < 4; a++)
#pragma unroll
        for (int b = 0; b < 4; b++) acc[a][b] = 0.f;

#pragma unroll 4
    for (int k = 0; k < HH; k++) {
        float4 hv = *(const float4*)&hsT[k][eg * 4];
        float4 wv = *(const float4*)&ws[k][og * 4];
        acc[0][0] += hv.x * wv.x; acc[0][1] += hv.x * wv.y; acc[0][2] += hv.x * wv.z; acc[0][3] += hv.x * wv.w;
        acc[1][0] += hv.y * wv.x; acc[1][1] += hv.y * wv.y; acc[1][2] += hv.y * wv.z; acc[1][3] += hv.y * wv.w;
        acc[2][0] += hv.z * wv.x; acc[2][1] += hv.z * wv.y; acc[2][2] += hv.z * wv.z; acc[2][3] += hv.z * wv.w;
        acc[3][0] += hv.w * wv.x; acc[3][1] += hv.w * wv.y; acc[3][2] += hv.w * wv.z; acc[3][3] += hv.w * wv.w;
    }

#pragma unroll
    for (int a = 0; a < 4; a++) {
        int le = eg * 4 + a;
        int d = sdst[le];
        if (d >= 0) {
            float* dr = hout + d * HH + og * 4;
            atomicAdd(dr + 0, acc[a][0]);
            atomicAdd(dr + 1, acc[a][1]);
            atomicAdd(dr + 2, acc[a][2]);
            atomicAdd(dr + 3, acc[a][3]);
        }
    }
}

// NOTE: the staging above needs src/dst pointers; simplest correct route is a
// dedicated gather kernel writing per-permuted-edge src/dst into globals once.
__device__ int g_psrc[EE];
__device__ int g_pdst[EE];
__global__ void k_permsd(const int* __restrict__ src, const int* __restrict__ dst) {
    int i = blockIdx.x * blockDim.x + threadIdx.x;
    if (i < EE) {
        int e = g_perm[i];
        g_psrc[i] = src[e];
        g_pdst[i] = dst[e];
    }
}

// ---------------- Set2Set LSTM cell ----------------------------------------
__global__ void k_lstm(const float* __restrict__ W_ih,
                       const float* __restrict__ W_hh,
                       const float* __restrict__ b_ih,
                       const float* __restrict__ b_hh) {
    int b = blockIdx.x;
    int j = threadIdx.x;
    __shared__ float qs[2 * HH];
    __shared__ float hs[HH];
    __shared__ float gates[4 * HH];
    if (j < 2 * HH) qs[j] = g_qstar[b * 2 * HH + j];
    if (j < HH) hs[j] = g_hx[b * HH + j];
    __syncthreads();
    float g = b_ih[j] + b_hh[j];
    const float* wi = W_ih + j * 2 * HH;
#pragma unroll 8
    for (int k = 0; k < 2 * HH; k++) g += qs[k] * wi[k];
    const float* wh = W_hh + j * HH;
#pragma unroll 8
    for (int k = 0; k < HH; k++) g += hs[k] * wh[k];
    gates[j] = g;
    __syncthreads();
    if (j < HH) {
        float ig = gates[j], fg = gates[HH + j], gg = gates[2 * HH + j], og = gates[3 * HH + j];
        float si = 1.f / (1.f + expf(-ig));
        float sf = 1.f / (1.f + expf(-fg));
        float so = 1.f / (1.f + expf(-og));
        float c = sf * g_cx[b * HH + j] + si * tanhf(gg);
        g_cx[b * HH + j] = c;
        g_hx[b * HH + j] = so * tanhf(c);
    }
}

// ---------------- attention pooling (one block per graph, 256 threads) -----
__global__ void k_attn() {
    const float* h = g_hB;
    int b = blockIdx.x;
    int tid = threadIdx.x;        // 256
    __shared__ float q[HH];
    __shared__ float red[256];
    __shared__ float r4[4][HH];
    if (tid < HH) q[tid] = g_hx[b * HH + tid];
    __syncthreads();
    int s = g_seg[b], t = g_seg[b + 1];

    float lmax = -1e30f;
    const float4* q4 = (const float4*)q;
    for (int n = s + tid; n < t; n += 256) {
        const float4* hr = (const float4*)(h + n * HH);
        float e = 0.f;
#pragma unroll
        for (int k = 0; k < HH / 4; k++) {
            float4 hv = hr[k];
            float4 qv = q4[k];
            e += hv.x * qv.x + hv.y * qv.y + hv.z * qv.z + hv.w * qv.w;
        }
        g_e[n] = e;
        lmax = fmaxf(lmax, e);
    }
    red[tid] = lmax; __syncthreads();
    for (int w = 128; w > 0; w >>= 1) {
        if (tid < w) red[tid] = fmaxf(red[tid], red[tid + w]);
        __syncthreads();
    }
    float m = red[0];
    __syncthreads();

    float lsum = 0.f;
    for (int n = s + tid; n < t; n += 256) {
        float a = expf(g_e[n] - m);
        g_a[n] = a;
        lsum += a;
    }
    red[tid] = lsum; __syncthreads();
    for (int w = 128; w > 0; w >>= 1) {
        if (tid < w) red[tid] += red[tid + w];
        __syncthreads();
    }
    float denom = red[0];
    if (denom == 0.f) denom = 1.f;
    __syncthreads();

    {
        int part = tid >> 6;      // 0..3
        int o = tid & 63;
        float r = 0.f;
        for (int n = s + part; n < t; n += 4) r += g_a[n] * h[n * HH + o];
        r4[part][o] = r;
    }
    __syncthreads();
    if (tid < HH) {
        g_qstar[b * 2 * HH + tid]      = q[tid];
        g_qstar[b * 2 * HH + HH + tid] =
            (r4[0][tid] + r4[1][tid] + r4[2][tid] + r4[3][tid]) / denom;
    }
}

// ---------------- output MLP -----------------------------------------------
__global__ void k_out(const float* __restrict__ W_o1,
                      const float* __restrict__ b_o1,
                      const float* __restrict__ W_o2,
                      const float* __restrict__ b_o2,
                      float* __restrict__ out) {
    int b = blockIdx.x;
    int j = threadIdx.x;
    __shared__ float qs[2 * HH];
    __shared__ float red[HH];
    qs[j] = g_qstar[b * 2 * HH + j];
    qs[HH + j] = g_qstar[b * 2 * HH + HH + j];
    __syncthreads();
    float t = b_o1[j];
#pragma unroll 8
    for (int k = 0; k < 2 * HH; k++) t += qs[k] * W_o1[k * HH + j];
    t = fmaxf(t, 0.f);
    red[j] = t * W_o2[j];
    __syncthreads();
    for (int w = 32; w > 0; w >>= 1) {
        if (j < w) red[j] += red[j + w];
        __syncthreads();
    }
    if (j == 0) out[b] = red[0] + b_o2[0];
}

// ---------------- edge GEMM (clean version using g_psrc/g_pdst) ------------
__global__ __launch_bounds__(256) void k_edge2(int flip) {
    const float* hin = flip ? g_hB : g_hA;
    float* hout      = flip ? g_hA : g_hB;

    __shared__ float hsT[HH][68];
    __shared__ float ws[HH][HH];
    __shared__ int   sdst[TE];
    __shared__ int   ssrc[TE];

    int bid = blockIdx.x;
    if (bid >= g_tileoff[EDIM]) return;

    int t = 0;
    while (bid >= g_tileoff[t + 1]) t++;
    int tile = bid - g_tileoff[t];
    int base = g_toff[t] + tile * TE;
    int count = g_toff[t + 1] - base;
    if (count > TE) count = TE;

    int tid = threadIdx.x;
    if (tid < TE) {
        if (tid < count) {
            ssrc[tid] = g_psrc[base + tid];
            sdst[tid] = g_pdst[base + tid];
        } else {
            ssrc[tid] = 0;
            sdst[tid] = -1;
        }
    }

    const float* W = g_Wmat + t * HH * HH;
    for (int i = tid; i < HH * HH; i += 256)
        ((float*)ws)[i] = W[i];
    __syncthreads();

    {
        int e = tid >> 2;
        int q = tid & 3;
        int s = ssrc[e];
        const float4* hr = (const float4*)(hin + s * HH + q * 16);
#pragma unroll
        for (int j = 0; j < 4; j++) {
            float4 v = hr[j];
            int k = q * 16 + j * 4;
            hsT[k + 0][e] = v.x;
            hsT[k + 1][e] = v.y;
            hsT[k + 2][e] = v.z;
            hsT[k + 3][e] = v.w;
        }
    }
    __syncthreads();

    int eg = tid >> 4;
    int og = tid & 15;
    float acc[4][4];
#pragma unroll
    for (int a = 0; a < 4; a++)
#pragma unroll
        for (int b = 0; b < 4; b++) acc[a][b] = 0.f;

#pragma unroll 4
    for (int k = 0; k < HH; k++) {
        float4 hv = *(const float4*)&hsT[k][eg * 4];
        float4 wv = *(const float4*)&ws[k][og * 4];
        acc[0][0] += hv.x * wv.x; acc[0][1] += hv.x * wv.y; acc[0][2] += hv.x * wv.z; acc[0][3] += hv.x * wv.w;
        acc[1][0] += hv.y * wv.x; acc[1][1] += hv.y * wv.y; acc[1][2] += hv.y * wv.z; acc[1][3] += hv.y * wv.w;
        acc[2][0] += hv.z * wv.x; acc[2][1] += hv.z * wv.y; acc[2][2] += hv.z * wv.z; acc[2][3] += hv.z * wv.w;
        acc[3][0] += hv.w * wv.x; acc[3][1] += hv.w * wv.y; acc[3][2] += hv.w * wv.z; acc[3][3] += hv.w * wv.w;
    }

#pragma unroll
    for (int a = 0; a < 4; a++) {
        int le = eg * 4 + a;
        int d = sdst[le];
        if (d >= 0) {
            float* dr = hout + d * HH + og * 4;
            atomicAdd(dr + 0, acc[a][0]);
            atomicAdd(dr + 1, acc[a][1]);
            atomicAdd(dr + 2, acc[a][2]);
            atomicAdd(dr + 3, acc[a][3]);
        }
    }
}

// ---------------------------------------------------------------------------
extern "C" void kernel_launch(void* const* d_in, const int* in_sizes, int n_in,
                              void* d_out, int out_size) {
    const float* node_feat = (const float*)d_in[0];
    const int*   node_type = (const int*)d_in[1];
    const int*   edge_index= (const int*)d_in[2];
    const int*   etype     = (const int*)d_in[3];
    const int*   batch     = (const int*)d_in[4];
    const float* W_emb     = (const float*)d_in[5];
    const float* b_emb     = (const float*)d_in[6];
    const float* W_e1      = (const float*)d_in[7];
    const float* b_e1      = (const float*)d_in[8];
    const float* W_e2      = (const float*)d_in[9];
    const float* b_e2      = (const float*)d_in[10];
    const float* roots     = (const float*)d_in[11];
    const float* conv_bias = (const float*)d_in[12];
    const float* W_ih      = (const float*)d_in[13];
    const float* W_hh      = (const float*)d_in[14];
    const float* b_ih      = (const float*)d_in[15];
    const float* b_hh      = (const float*)d_in[16];
    const float* W_o1      = (const float*)d_in[17];
    const float* b_o1      = (const float*)d_in[18];
    const float* W_o2      = (const float*)d_in[19];
    const float* b_o2      = (const float*)d_in[20];
    float* out = (float*)d_out;

    const int* src = edge_index;
    const int* dst = edge_index + EE;

    k_init<<<(BB * 2 * HH + 255) / 256, 256>>>();
    k_seg<<<1, 160>>>(batch);
    k_hist<<<(EE + 255) / 256, 256>>>(etype);
    k_scan<<<1, 1>>>();
    k_scatter<<<(EE + 255) / 256, 256>>>(etype);
    k_permsd<<<(EE + 255) / 256, 256>>>(src, dst);
    k_embed<<<NN / 4, 256>>>(node_feat, node_type, W_emb, b_emb);
    k_wmat<<<64, 256>>>(W_e1, b_e1, W_e2, b_e2);

    for (int i = 0; i < MPI; i++) {
        int flip = i & 1;              // 0: A->B, 1: B->A, 2: A->B (final in g_hB)
        k_root<<<NN / 4, 256>>>(flip, i, roots, conv_bias);
        k_edge2<<<MAXTILES, 256>>>(flip);
    }

    for (int s = 0; s < S2S; s++) {
        k_lstm<<<BB, 256>>>(W_ih, W_hh, b_ih, b_hh);
        k_attn<<<BB, 256>>>();
    }

    k_out<<<BB, 64>>>(W_o1, b_o1, W_o2, b_o2, out);
}